// round 7
// baseline (speedup 1.0000x reference)
#include <cuda_runtime.h>
#include <math.h>
#include <stdint.h>

#define B_  2
#define S_  1024
#define P_  1024
#define D_  1024
#define H_  16
#define DH_ 64
#define T_  2048   // P + S
#define NT_ 2048   // B * S tokens
#define D3_ 3072
#define D4_ 4096

// ---------------- scratch ----------------
// A-side buffers hold tf32 bits, K-dim permuted within 8-groups (pc8).
__device__ uint32_t g_h   [NT_ * D_];
__device__ float    g_qkv [NT_ * D3_];       // unpermuted fp32
__device__ float    g_Kall[B_*H_*DH_*T_];    // [b,h,d,t]
__device__ float    g_Vall[B_*H_*T_*DH_];    // [b,h,t,d]
__device__ uint32_t g_a   [NT_ * D_];
__device__ float    g_x1  [NT_ * D_];
__device__ uint32_t g_h2  [NT_ * D_];
__device__ uint32_t g_m   [NT_ * D4_];
// weights: tf32 bits, N-dim permuted within 64-groups (swap 3-bit fields)
__device__ uint32_t g_wattn_t[D_ * D3_];
__device__ uint32_t g_wproj_t[D_ * D_];
__device__ uint32_t g_wfc_t  [D_ * D4_];
__device__ uint32_t g_wfc2_t [D4_ * D_];

// ---------------- helpers ----------------
__device__ __forceinline__ uint32_t smem_u32(const void* p) {
    return (uint32_t)__cvta_generic_to_shared(p);
}
__device__ __forceinline__ void cp_async16(uint32_t saddr, const void* g) {
    asm volatile("cp.async.cg.shared.global [%0], [%1], 16;\n" :: "r"(saddr), "l"(g));
}
__device__ __forceinline__ void cp_commit() {
    asm volatile("cp.async.commit_group;\n");
}
template<int N>
__device__ __forceinline__ void cp_wait() {
    asm volatile("cp.async.wait_group %0;\n" :: "n"(N));
}
__device__ __forceinline__ uint32_t f2tf(float v) {
    uint32_t r;
    asm("cvt.rna.tf32.f32 %0, %1;" : "=r"(r) : "f"(v));
    return r;
}
// K-dim permutation within 8-groups: cols {tq, tq+4} -> {2tq, 2tq+1}
__device__ __forceinline__ int pc8(int o) {
    return (o & ~7) | ((o & 3) << 1) | ((o >> 2) & 1);
}
__device__ __forceinline__ void mma_tf32(float* d, const uint32_t* a, const uint32_t* b) {
    asm volatile(
        "mma.sync.aligned.m16n8k8.row.col.f32.tf32.tf32.f32 "
        "{%0,%1,%2,%3}, {%4,%5,%6,%7}, {%8,%9}, {%0,%1,%2,%3};"
        : "+f"(d[0]), "+f"(d[1]), "+f"(d[2]), "+f"(d[3])
        : "r"(a[0]), "r"(a[1]), "r"(a[2]), "r"(a[3]), "r"(b[0]), "r"(b[1]));
}
__device__ __forceinline__ float gelu_f(float x) {
    float x3 = x * x * x;
    return 0.5f * x * (1.0f + tanhf(0.7978845608028654f * (x + 0.044715f * x3)));
}

// ---------------- weight conversion + N-dim 64-group permutation ----------------
// dst[row][c] = tf32(src[row][grp64(c) | ((c&7)<<3) | ((c&63)>>3)])  (involution)
__global__ void conv_perm_kernel(const float* __restrict__ src, uint32_t* __restrict__ dst,
                                 int N, int total4) {
    int i = blockIdx.x * blockDim.x + threadIdx.x;
    if (i >= total4) return;
    int e = i * 4;
    int row = e / N, col = e % N;
    size_t rb = (size_t)row * N;
    int grp = col & ~63;
    uint4 o4;
    {
        int o = (col & 63);
        o4.x = f2tf(src[rb + (grp | ((o & 7) << 3) | (o >> 3))]);
        o++;
        o4.y = f2tf(src[rb + (grp | ((o & 7) << 3) | (o >> 3))]);
        o++;
        o4.z = f2tf(src[rb + (grp | ((o & 7) << 3) | (o >> 3))]);
        o++;
        o4.w = f2tf(src[rb + (grp | ((o & 7) << 3) | (o >> 3))]);
    }
    *(uint4*)&dst[rb + col] = o4;
}

// ---------------- layernorm -> tf32 bits, pc8-permuted cols ----------------
__global__ void ln_kernel(const float* __restrict__ X, const float* __restrict__ w,
                          const float* __restrict__ bia, uint32_t* __restrict__ Y) {
    __shared__ float red1[8];
    __shared__ float red2[8];
    int row = blockIdx.x;
    int tid = threadIdx.x;
    float4 v = ((const float4*)(X + (size_t)row * D_))[tid];
    float s = v.x + v.y + v.z + v.w;
    #pragma unroll
    for (int o = 16; o; o >>= 1) s += __shfl_xor_sync(0xffffffffu, s, o);
    if ((tid & 31) == 0) red1[tid >> 5] = s;
    __syncthreads();
    float u = 0.f;
    #pragma unroll
    for (int i = 0; i < 8; i++) u += red1[i];
    u *= (1.0f / D_);
    float dx = v.x - u, dy = v.y - u, dz = v.z - u, dw = v.w - u;
    float q = dx*dx + dy*dy + dz*dz + dw*dw;
    #pragma unroll
    for (int o = 16; o; o >>= 1) q += __shfl_xor_sync(0xffffffffu, q, o);
    if ((tid & 31) == 0) red2[tid >> 5] = q;
    __syncthreads();
    float var = 0.f;
    #pragma unroll
    for (int i = 0; i < 8; i++) var += red2[i];
    var *= (1.0f / D_);
    float inv = rsqrtf(var + 1e-12f);
    float4 wv = ((const float4*)w)[tid];
    float4 bv = ((const float4*)bia)[tid];
    uint32_t* Yr = Y + (size_t)row * D_;
    int c0 = tid * 4;
    int base = c0 & ~7, hb = (c0 >> 2) & 1;
    Yr[base | (0 << 1) | hb] = f2tf(wv.x * (dx * inv) + bv.x);
    Yr[base | (1 << 1) | hb] = f2tf(wv.y * (dy * inv) + bv.y);
    Yr[base | (2 << 1) | hb] = f2tf(wv.z * (dz * inv) + bv.z);
    Yr[base | (3 << 1) | hb] = f2tf(wv.w * (dw * inv) + bv.w);
}

// ---------------- tf32 GEMM: 128x128x16 tile, 3-stage pipeline ----------------
// A: pc8-permuted K-dim; B: 64-group swapped N-dim. Vectorized fragment loads.
#define ASTG 2560   // 128*20
#define BSTG 2176   // 16*136
#define TG_SMEM (3 * (ASTG + BSTG) * 4)

template<int EPI, int OTF>
__global__ __launch_bounds__(256)
void tgemm_kernel(const uint32_t* __restrict__ A, const uint32_t* __restrict__ W,
                  const float* __restrict__ bias, const float* __restrict__ R,
                  float* __restrict__ C, int M, int N, int K) {
    extern __shared__ uint32_t smg[];
    uint32_t* sA = smg;
    uint32_t* sB = smg + 3 * ASTG;

    int tid = threadIdx.x, lane = tid & 31, wid = tid >> 5;
    int wm = wid >> 1, wn = wid & 1;
    int row0 = blockIdx.y * 128, col0 = blockIdx.x * 128;
    int g = lane >> 2, tq = lane & 3;

    float acc[2][8][4];
    #pragma unroll
    for (int mi = 0; mi < 2; mi++)
        #pragma unroll
        for (int ni = 0; ni < 8; ni++)
            #pragma unroll
            for (int r = 0; r < 4; r++) acc[mi][ni][r] = 0.f;

    auto prefetch = [&](int st, int k0) {
        #pragma unroll
        for (int i = 0; i < 2; i++) {
            int c = tid + 256 * i;
            int ar = c >> 2, ac = (c & 3) << 2;
            cp_async16(smem_u32(&sA[st * ASTG + ar * 20 + ac]),
                       A + (size_t)(row0 + ar) * K + k0 + ac);
            int br = c >> 5, bc = (c & 31) << 2;
            cp_async16(smem_u32(&sB[st * BSTG + br * 136 + bc]),
                       W + (size_t)(k0 + br) * N + col0 + bc);
        }
        cp_commit();
    };

    int NK = K >> 4;
    prefetch(0, 0);
    prefetch(1, 16);
    for (int kt = 0; kt < NK; kt++) {
        if (kt + 1 < NK) cp_wait<1>(); else cp_wait<0>();
        __syncthreads();
        if (kt + 2 < NK) prefetch((kt + 2) % 3, (kt + 2) << 4);

        int st = kt % 3;
        const uint32_t* pa = sA + st * ASTG;
        const uint32_t* pb = sB + st * BSTG;
        #pragma unroll
        for (int kk = 0; kk < 16; kk += 8) {
            uint32_t af[2][4];
            #pragma unroll
            for (int mi = 0; mi < 2; mi++) {
                int mb = wm * 32 + mi * 16;
                uint2 a0 = *(const uint2*)&pa[(mb + g) * 20 + kk + 2 * tq];
                uint2 a1 = *(const uint2*)&pa[(mb + g + 8) * 20 + kk + 2 * tq];
                af[mi][0] = a0.x; af[mi][2] = a0.y;
                af[mi][1] = a1.x; af[mi][3] = a1.y;
            }
            const uint32_t* rl = &pb[(kk + tq) * 136 + wn * 64 + g * 8];
            const uint32_t* rh = &pb[(kk + tq + 4) * 136 + wn * 64 + g * 8];
            uint4 b0 = *(const uint4*)rl;
            uint4 b1 = *(const uint4*)(rl + 4);
            uint4 b2 = *(const uint4*)rh;
            uint4 b3 = *(const uint4*)(rh + 4);
            uint32_t blo[8] = {b0.x, b0.y, b0.z, b0.w, b1.x, b1.y, b1.z, b1.w};
            uint32_t bhi[8] = {b2.x, b2.y, b2.z, b2.w, b3.x, b3.y, b3.z, b3.w};
            #pragma unroll
            for (int mi = 0; mi < 2; mi++)
                #pragma unroll
                for (int ni = 0; ni < 8; ni++) {
                    uint32_t bf[2] = {blo[ni], bhi[ni]};
                    mma_tf32(acc[mi][ni], af[mi], bf);
                }
        }
    }

    #pragma unroll
    for (int mi = 0; mi < 2; mi++) {
        int rA = row0 + wm * 32 + mi * 16 + g;
        int rB = rA + 8;
        #pragma unroll
        for (int ni = 0; ni < 8; ni++) {
            int cg = col0 + wn * 64 + ni * 8 + 2 * tq;
            float b0 = bias[cg], b1 = bias[cg + 1];
            float v0 = acc[mi][ni][0] + b0;
            float v1 = acc[mi][ni][1] + b1;
            float v2 = acc[mi][ni][2] + b0;
            float v3 = acc[mi][ni][3] + b1;
            if (EPI == 1) {
                v0 = gelu_f(v0); v1 = gelu_f(v1);
                v2 = gelu_f(v2); v3 = gelu_f(v3);
            }
            if (EPI == 2) {
                v0 += R[(size_t)rA * N + cg];
                v1 += R[(size_t)rA * N + cg + 1];
                v2 += R[(size_t)rB * N + cg];
                v3 += R[(size_t)rB * N + cg + 1];
            }
            if (OTF) {  // tf32 bits, pc8-permuted (feeds next GEMM's A)
                uint32_t* Cu = (uint32_t*)C;
                Cu[(size_t)rA * N + pc8(cg)]     = f2tf(v0);
                Cu[(size_t)rA * N + pc8(cg + 1)] = f2tf(v1);
                Cu[(size_t)rB * N + pc8(cg)]     = f2tf(v2);
                Cu[(size_t)rB * N + pc8(cg + 1)] = f2tf(v3);
            } else {
                *(float2*)&C[(size_t)rA * N + cg] = make_float2(v0, v1);
                *(float2*)&C[(size_t)rB * N + cg] = make_float2(v2, v3);
            }
        }
    }
}

// ---------------- KV assembly ----------------
__global__ void copy_past_k(const float* __restrict__ kin) {
    int idx = blockIdx.x * blockDim.x + threadIdx.x;
    int e = idx * 4;
    int bhd = e >> 10;
    int t   = e & 1023;
    *(float4*)&g_Kall[(size_t)bhd * T_ + t] = *(const float4*)&kin[e];
}

__global__ void copy_past_v(const float* __restrict__ vin) {
    int idx = blockIdx.x * blockDim.x + threadIdx.x;
    int e = idx * 4;
    int bh  = e >> 16;
    int rem = e & 65535;
    *(float4*)&g_Vall[(size_t)bh * T_ * DH_ + rem] = *(const float4*)&vin[e];
}

__global__ void scatter_kv(const float* __restrict__ qkv,
                           float* __restrict__ outk, float* __restrict__ outv) {
    int idx = blockIdx.x * blockDim.x + threadIdx.x;
    int bs = idx >> 10;
    int hd = idx & 1023;
    int b = bs >> 10, s = bs & 1023;
    int h = hd >> 6,  d = hd & 63;
    float kkv = qkv[(size_t)bs * D3_ + D_     + hd];
    float vvv = qkv[(size_t)bs * D3_ + 2 * D_ + hd];
    size_t kpos = (size_t)(b * H_ + h) * DH_ + d;
    g_Kall[kpos * T_ + P_ + s] = kkv;
    outk[kpos * S_ + s] = kkv;
    size_t vrow = (size_t)(b * H_ + h) * T_ + P_ + s;
    g_Vall[vrow * DH_ + d] = vvv;
    outv[((size_t)(b * H_ + h) * S_ + s) * DH_ + d] = vvv;
}

// ---------------- flash attention, tf32 MMA, permuted smem tiles ----------------
__global__ __launch_bounds__(128)
void attn_mma_kernel(const float* __restrict__ qkv, uint32_t* __restrict__ Ab) {
    extern __shared__ uint32_t smu[];
    uint32_t (*Qs)[72] = (uint32_t(*)[72])smu;                  // pc8-permuted d
    uint32_t (*Ks)[72] = (uint32_t(*)[72])(smu + 64 * 72);      // [d][key'], 64-swap keys
    uint32_t (*Vs)[72] = (uint32_t(*)[72])(smu + 2 * 64 * 72);  // [key][d'], 64-swap d

    int bh = blockIdx.x, b = bh >> 4, h = bh & 15;
    int s0 = blockIdx.y * 64;
    int tid = threadIdx.x, lane = tid & 31, wid = tid >> 5;
    int g = lane >> 2, tq = lane & 3;
    int mb = wid * 16;

    for (int it = tid; it < 1024; it += 128) {
        int r = it >> 4, c = (it & 15) << 2;
        float4 v = *(const float4*)&qkv[(size_t)(b * S_ + s0 + r) * D3_ + h * DH_ + c];
        int base = c & ~7, hb = (c >> 2) & 1;
        Qs[r][base | (0 << 1) | hb] = f2tf(v.x);
        Qs[r][base | (1 << 1) | hb] = f2tf(v.y);
        Qs[r][base | (2 << 1) | hb] = f2tf(v.z);
        Qs[r][base | (3 << 1) | hb] = f2tf(v.w);
    }
    const float* Kb = g_Kall + (size_t)bh * DH_ * T_;
    const float* Vb = g_Vall + (size_t)bh * T_ * DH_;

    float m0 = -INFINITY, m1 = -INFINITY, l0 = 0.f, l1 = 0.f;
    float O[8][4];
    #pragma unroll
    for (int nd = 0; nd < 8; nd++)
        #pragma unroll
        for (int r = 0; r < 4; r++) O[nd][r] = 0.f;

    for (int t0 = 0; t0 < T_; t0 += 64) {
        __syncthreads();
        for (int it = tid; it < 1024; it += 128) {
            int r = it >> 4, c = (it & 15) << 2;
            float4 kv = *(const float4*)&Kb[(size_t)r * T_ + t0 + c];
            float4 vv = *(const float4*)&Vb[(size_t)(t0 + r) * DH_ + c];
            int hi = c >> 3, lo = c & 7;  // 64-swap: o=c+j -> ((lo+j)<<3)|hi
            Ks[r][((lo + 0) << 3) | hi] = f2tf(kv.x);
            Ks[r][((lo + 1) << 3) | hi] = f2tf(kv.y);
            Ks[r][((lo + 2) << 3) | hi] = f2tf(kv.z);
            Ks[r][((lo + 3) << 3) | hi] = f2tf(kv.w);
            Vs[r][((lo + 0) << 3) | hi] = f2tf(vv.x);
            Vs[r][((lo + 1) << 3) | hi] = f2tf(vv.y);
            Vs[r][((lo + 2) << 3) | hi] = f2tf(vv.z);
            Vs[r][((lo + 3) << 3) | hi] = f2tf(vv.w);
        }
        __syncthreads();

        float sv[8][4];
        #pragma unroll
        for (int ni = 0; ni < 8; ni++)
            #pragma unroll
            for (int r = 0; r < 4; r++) sv[ni][r] = 0.f;

        #pragma unroll
        for (int kk = 0; kk < 64; kk += 8) {
            uint32_t af[4];
            uint2 q0 = *(const uint2*)&Qs[mb + g][kk + 2 * tq];
            uint2 q1 = *(const uint2*)&Qs[mb + g + 8][kk + 2 * tq];
            af[0] = q0.x; af[2] = q0.y;
            af[1] = q1.x; af[3] = q1.y;
            uint4 k0 = *(const uint4*)&Ks[kk + tq][g * 8];
            uint4 k1 = *(const uint4*)&Ks[kk + tq][g * 8 + 4];
            uint4 k2 = *(const uint4*)&Ks[kk + tq + 4][g * 8];
            uint4 k3 = *(const uint4*)&Ks[kk + tq + 4][g * 8 + 4];
            uint32_t blo[8] = {k0.x, k0.y, k0.z, k0.w, k1.x, k1.y, k1.z, k1.w};
            uint32_t bhi[8] = {k2.x, k2.y, k2.z, k2.w, k3.x, k3.y, k3.z, k3.w};
            #pragma unroll
            for (int ni = 0; ni < 8; ni++) {
                uint32_t bf[2] = {blo[ni], bhi[ni]};
                mma_tf32(sv[ni], af, bf);
            }
        }

        float mx0 = -INFINITY, mx1 = -INFINITY;
        #pragma unroll
        for (int ni = 0; ni < 8; ni++) {
            mx0 = fmaxf(mx0, fmaxf(sv[ni][0], sv[ni][1]));
            mx1 = fmaxf(mx1, fmaxf(sv[ni][2], sv[ni][3]));
        }
        mx0 = fmaxf(mx0, __shfl_xor_sync(0xffffffffu, mx0, 1));
        mx0 = fmaxf(mx0, __shfl_xor_sync(0xffffffffu, mx0, 2));
        mx1 = fmaxf(mx1, __shfl_xor_sync(0xffffffffu, mx1, 1));
        mx1 = fmaxf(mx1, __shfl_xor_sync(0xffffffffu, mx1, 2));
        float mn0 = fmaxf(m0, mx0), mn1 = fmaxf(m1, mx1);
        float sc0 = __expf(m0 - mn0), sc1 = __expf(m1 - mn1);
        float ps0 = 0.f, ps1 = 0.f;
        #pragma unroll
        for (int ni = 0; ni < 8; ni++) {
            sv[ni][0] = __expf(sv[ni][0] - mn0);
            sv[ni][1] = __expf(sv[ni][1] - mn0);
            sv[ni][2] = __expf(sv[ni][2] - mn1);
            sv[ni][3] = __expf(sv[ni][3] - mn1);
            ps0 += sv[ni][0] + sv[ni][1];
            ps1 += sv[ni][2] + sv[ni][3];
        }
        ps0 += __shfl_xor_sync(0xffffffffu, ps0, 1);
        ps0 += __shfl_xor_sync(0xffffffffu, ps0, 2);
        ps1 += __shfl_xor_sync(0xffffffffu, ps1, 1);
        ps1 += __shfl_xor_sync(0xffffffffu, ps1, 2);
        l0 = l0 * sc0 + ps0;
        l1 = l1 * sc1 + ps1;
        m0 = mn0; m1 = mn1;
        #pragma unroll
        for (int nd = 0; nd < 8; nd++) {
            O[nd][0] *= sc0; O[nd][1] *= sc0;
            O[nd][2] *= sc1; O[nd][3] *= sc1;
        }

        #pragma unroll
        for (int ni = 0; ni < 8; ni++) {
            int sl0 = (g << 2) + (tq >> 1);
            int sl1 = sl0 + 2;
            float v00 = __shfl_sync(0xffffffffu, sv[ni][0], sl0);
            float v01 = __shfl_sync(0xffffffffu, sv[ni][1], sl0);
            float v10 = __shfl_sync(0xffffffffu, sv[ni][0], sl1);
            float v11 = __shfl_sync(0xffffffffu, sv[ni][1], sl1);
            float w00 = __shfl_sync(0xffffffffu, sv[ni][2], sl0);
            float w01 = __shfl_sync(0xffffffffu, sv[ni][3], sl0);
            float w10 = __shfl_sync(0xffffffffu, sv[ni][2], sl1);
            float w11 = __shfl_sync(0xffffffffu, sv[ni][3], sl1);
            bool odd = (tq & 1);
            uint32_t af[4];
            af[0] = f2tf(odd ? v01 : v00);
            af[1] = f2tf(odd ? w01 : w00);
            af[2] = f2tf(odd ? v11 : v10);
            af[3] = f2tf(odd ? w11 : w10);
            uint4 w0 = *(const uint4*)&Vs[ni * 8 + tq][g * 8];
            uint4 w1 = *(const uint4*)&Vs[ni * 8 + tq][g * 8 + 4];
            uint4 w2 = *(const uint4*)&Vs[ni * 8 + tq + 4][g * 8];
            uint4 w3 = *(const uint4*)&Vs[ni * 8 + tq + 4][g * 8 + 4];
            uint32_t vlo[8] = {w0.x, w0.y, w0.z, w0.w, w1.x, w1.y, w1.z, w1.w};
            uint32_t vhi[8] = {w2.x, w2.y, w2.z, w2.w, w3.x, w3.y, w3.z, w3.w};
            #pragma unroll
            for (int nd = 0; nd < 8; nd++) {
                uint32_t bf[2] = {vlo[nd], vhi[nd]};
                mma_tf32(O[nd], af, bf);
            }
        }
    }

    float inv0 = 1.0f / l0, inv1 = 1.0f / l1;
    int rA = s0 + mb + g, rB = rA + 8;
    uint32_t* rowA = &Ab[(size_t)(b * S_ + rA) * D_];
    uint32_t* rowB = &Ab[(size_t)(b * S_ + rB) * D_];
    #pragma unroll
    for (int nd = 0; nd < 8; nd++) {
        int col = h * DH_ + nd * 8 + 2 * tq;
        rowA[pc8(col)]     = f2tf(O[nd][0] * inv0);
        rowA[pc8(col + 1)] = f2tf(O[nd][1] * inv0);
        rowB[pc8(col)]     = f2tf(O[nd][2] * inv1);
        rowB[pc8(col + 1)] = f2tf(O[nd][3] * inv1);
    }
}

// ---------------- launch ----------------
extern "C" void kernel_launch(void* const* d_in, const int* in_sizes, int n_in,
                              void* d_out, int out_size) {
    const float* x      = (const float*)d_in[0];
    const float* kin    = (const float*)d_in[1];
    const float* vin    = (const float*)d_in[2];
    const float* ln1w   = (const float*)d_in[3];
    const float* ln1b   = (const float*)d_in[4];
    const float* ln2w   = (const float*)d_in[5];
    const float* ln2b   = (const float*)d_in[6];
    const float* w_attn = (const float*)d_in[7];
    const float* b_attn = (const float*)d_in[8];
    const float* w_proj = (const float*)d_in[9];
    const float* b_proj = (const float*)d_in[10];
    const float* w_fc   = (const float*)d_in[11];
    const float* b_fc   = (const float*)d_in[12];
    const float* w_fc2  = (const float*)d_in[13];
    const float* b_fc2  = (const float*)d_in[14];

    float* out_x = (float*)d_out;
    float* out_k = out_x + (size_t)NT_ * D_;
    float* out_v = out_k + (size_t)NT_ * D_;

    uint32_t *ph, *pa, *ph2, *pm, *pwa, *pwp, *pwf, *pwf2;
    float *pqkv, *px1;
    cudaGetSymbolAddress((void**)&ph,   g_h);
    cudaGetSymbolAddress((void**)&pqkv, g_qkv);
    cudaGetSymbolAddress((void**)&pa,   g_a);
    cudaGetSymbolAddress((void**)&px1,  g_x1);
    cudaGetSymbolAddress((void**)&ph2,  g_h2);
    cudaGetSymbolAddress((void**)&pm,   g_m);
    cudaGetSymbolAddress((void**)&pwa,  g_wattn_t);
    cudaGetSymbolAddress((void**)&pwp,  g_wproj_t);
    cudaGetSymbolAddress((void**)&pwf,  g_wfc_t);
    cudaGetSymbolAddress((void**)&pwf2, g_wfc2_t);

    cudaFuncSetAttribute(tgemm_kernel<0,0>, cudaFuncAttributeMaxDynamicSharedMemorySize, TG_SMEM);
    cudaFuncSetAttribute(tgemm_kernel<2,0>, cudaFuncAttributeMaxDynamicSharedMemorySize, TG_SMEM);
    cudaFuncSetAttribute(tgemm_kernel<1,1>, cudaFuncAttributeMaxDynamicSharedMemorySize, TG_SMEM);
    int attn_smem = 3 * 64 * 72 * (int)sizeof(uint32_t);  // 55296
    cudaFuncSetAttribute(attn_mma_kernel, cudaFuncAttributeMaxDynamicSharedMemorySize, attn_smem);

    // 1: w_attn conversion (permuted)
    conv_perm_kernel<<<(D_*D3_/4 + 255)/256, 256>>>(w_attn, pwa, D3_, D_*D3_/4);
    // 2: ln1
    ln_kernel<<<NT_, 256>>>(x, ln1w, ln1b, ph);
    // 3: past-K copy
    copy_past_k<<<2048, 256>>>(kin);
    // 4: qkv gemm  <-- profiled slot
    tgemm_kernel<0,0><<<dim3(D3_ / 128, NT_ / 128), 256, TG_SMEM>>>(ph, pwa, b_attn, nullptr,
                                                                    pqkv, NT_, D3_, D_);
    // 5: past-V copy
    copy_past_v<<<2048, 256>>>(vin);
    // 6: scatter new KV
    scatter_kv<<<8192, 256>>>(pqkv, out_k, out_v);
    // 7: attention
    attn_mma_kernel<<<dim3(B_ * H_, S_ / 64), 128, attn_smem>>>(pqkv, pa);
    // 8: w_proj conversion
    conv_perm_kernel<<<(D_*D_/4 + 255)/256, 256>>>(w_proj, pwp, D_, D_*D_/4);
    // 9: proj + residual
    tgemm_kernel<2,0><<<dim3(D_ / 128, NT_ / 128), 256, TG_SMEM>>>(pa, pwp, b_proj, x,
                                                                   px1, NT_, D_, D_);
    // 10: ln2
    ln_kernel<<<NT_, 256>>>(px1, ln2w, ln2b, ph2);
    // 11: w_fc conversion
    conv_perm_kernel<<<(D_*D4_/4 + 255)/256, 256>>>(w_fc, pwf, D4_, D_*D4_/4);
    // 12: fc + gelu -> tf32 permuted
    tgemm_kernel<1,1><<<dim3(D4_ / 128, NT_ / 128), 256, TG_SMEM>>>(ph2, pwf, b_fc, nullptr,
                                                                    (float*)pm, NT_, D4_, D_);
    // 13: w_fc2 conversion
    conv_perm_kernel<<<(D4_*D_/4 + 255)/256, 256>>>(w_fc2, pwf2, D_, D4_*D_/4);
    // 14: fc2 + residual -> out x
    tgemm_kernel<2,0><<<dim3(D_ / 128, NT_ / 128), 256, TG_SMEM>>>(pm, pwf2, b_fc2, px1,
                                                                   out_x, NT_, D_, D4_);
}

// round 10
// speedup vs baseline: 1.3672x; 1.3672x over previous
#include <cuda_runtime.h>
#include <math.h>
#include <stdint.h>

#define B_  2
#define S_  1024
#define P_  1024
#define D_  1024
#define H_  16
#define DH_ 64
#define T_  2048   // P + S
#define NT_ 2048   // B * S tokens
#define D3_ 3072
#define D4_ 4096

// ---------------- scratch ----------------
__device__ uint32_t g_h   [NT_ * D_];        // ln1 out (tf32 bits)
__device__ float    g_qkv [NT_ * D3_];
__device__ float    g_Kall[B_*H_*DH_*T_];    // [b,h,d,t]
__device__ float    g_Vall[B_*H_*T_*DH_];    // [b,h,t,d]
__device__ uint32_t g_a   [NT_ * D_];        // attn out (tf32 bits)
__device__ float    g_x1  [NT_ * D_];
__device__ uint32_t g_h2  [NT_ * D_];        // ln2 out (tf32 bits)
__device__ uint32_t g_m   [NT_ * D4_];       // mlp hidden (tf32 bits)
__device__ uint32_t g_wattn_t[D_ * D3_];
__device__ uint32_t g_wproj_t[D_ * D_];
__device__ uint32_t g_wfc_t  [D_ * D4_];
__device__ uint32_t g_wfc2_t [D4_ * D_];

// ---------------- helpers ----------------
__device__ __forceinline__ uint32_t smem_u32(const void* p) {
    return (uint32_t)__cvta_generic_to_shared(p);
}
__device__ __forceinline__ void cp_async16(uint32_t saddr, const void* g) {
    asm volatile("cp.async.cg.shared.global [%0], [%1], 16;\n" :: "r"(saddr), "l"(g));
}
__device__ __forceinline__ void cp_commit() {
    asm volatile("cp.async.commit_group;\n");
}
template<int N>
__device__ __forceinline__ void cp_wait() {
    asm volatile("cp.async.wait_group %0;\n" :: "n"(N));
}
__device__ __forceinline__ uint32_t f2tf(float v) {
    uint32_t r;
    asm("cvt.rna.tf32.f32 %0, %1;" : "=r"(r) : "f"(v));
    return r;
}
__device__ __forceinline__ void mma_tf32(float* d, const uint32_t* a, const uint32_t* b) {
    asm volatile(
        "mma.sync.aligned.m16n8k8.row.col.f32.tf32.tf32.f32 "
        "{%0,%1,%2,%3}, {%4,%5,%6,%7}, {%8,%9}, {%0,%1,%2,%3};"
        : "+f"(d[0]), "+f"(d[1]), "+f"(d[2]), "+f"(d[3])
        : "r"(a[0]), "r"(a[1]), "r"(a[2]), "r"(a[3]), "r"(b[0]), "r"(b[1]));
}
__device__ __forceinline__ float gelu_f(float x) {
    float x3 = x * x * x;
    return 0.5f * x * (1.0f + tanhf(0.7978845608028654f * (x + 0.044715f * x3)));
}

// ---------------- weight pre-conversion ----------------
__global__ void conv_tf32_kernel(const float4* __restrict__ src, uint4* __restrict__ dst,
                                 int n4) {
    int i = blockIdx.x * blockDim.x + threadIdx.x;
    if (i < n4) {
        float4 v = src[i];
        uint4 o;
        o.x = f2tf(v.x); o.y = f2tf(v.y); o.z = f2tf(v.z); o.w = f2tf(v.w);
        dst[i] = o;
    }
}

// ---------------- layernorm -> tf32 bits ----------------
__global__ void ln_kernel(const float* __restrict__ X, const float* __restrict__ w,
                          const float* __restrict__ bia, uint32_t* __restrict__ Y) {
    __shared__ float red1[8];
    __shared__ float red2[8];
    int row = blockIdx.x;
    int tid = threadIdx.x;
    float4 v = ((const float4*)(X + (size_t)row * D_))[tid];
    float s = v.x + v.y + v.z + v.w;
    #pragma unroll
    for (int o = 16; o; o >>= 1) s += __shfl_xor_sync(0xffffffffu, s, o);
    if ((tid & 31) == 0) red1[tid >> 5] = s;
    __syncthreads();
    float u = 0.f;
    #pragma unroll
    for (int i = 0; i < 8; i++) u += red1[i];
    u *= (1.0f / D_);
    float dx = v.x - u, dy = v.y - u, dz = v.z - u, dw = v.w - u;
    float q = dx*dx + dy*dy + dz*dz + dw*dw;
    #pragma unroll
    for (int o = 16; o; o >>= 1) q += __shfl_xor_sync(0xffffffffu, q, o);
    if ((tid & 31) == 0) red2[tid >> 5] = q;
    __syncthreads();
    float var = 0.f;
    #pragma unroll
    for (int i = 0; i < 8; i++) var += red2[i];
    var *= (1.0f / D_);
    float inv = rsqrtf(var + 1e-12f);
    float4 wv = ((const float4*)w)[tid];
    float4 bv = ((const float4*)bia)[tid];
    uint4 o;
    o.x = f2tf(wv.x * (dx * inv) + bv.x);
    o.y = f2tf(wv.y * (dy * inv) + bv.y);
    o.z = f2tf(wv.z * (dz * inv) + bv.z);
    o.w = f2tf(wv.w * (dw * inv) + bv.w);
    ((uint4*)(Y + (size_t)row * D_))[tid] = o;
}

// ---------------- tf32 GEMM: 128x128x32 tile, 3-stage pipeline, 1 sync/chunk ---
// stage sizes (uint32): A 128x36 = 4608, B 32x136 = 4352
#define ASTG 4608
#define BSTG 4352
#define TG_SMEM (3 * (ASTG + BSTG) * 4)   // 107520

template<int EPI, int OTF>
__global__ __launch_bounds__(256)
void tgemm_kernel(const uint32_t* __restrict__ A, const uint32_t* __restrict__ W,
                  const float* __restrict__ bias, const float* __restrict__ R,
                  float* __restrict__ C, int M, int N, int K) {
    extern __shared__ uint32_t smg[];
    uint32_t* sA = smg;                 // 3 stages of A
    uint32_t* sB = smg + 3 * ASTG;      // 3 stages of B

    int tid = threadIdx.x, lane = tid & 31, wid = tid >> 5;
    int wm = wid >> 1, wn = wid & 1;
    int row0 = blockIdx.y * 128, col0 = blockIdx.x * 128;
    int g = lane >> 2, tq = lane & 3;

    float acc[2][8][4];
    #pragma unroll
    for (int mi = 0; mi < 2; mi++)
        #pragma unroll
        for (int ni = 0; ni < 8; ni++)
            #pragma unroll
            for (int r = 0; r < 4; r++) acc[mi][ni][r] = 0.f;

    auto prefetch = [&](int st, int k0) {
        #pragma unroll
        for (int i = 0; i < 4; i++) {
            int c = tid + 256 * i;                 // 0..1023
            int ar = c >> 3, ac = (c & 7) << 2;    // 128 rows x 32 cols
            cp_async16(smem_u32(&sA[st * ASTG + ar * 36 + ac]),
                       A + (size_t)(row0 + ar) * K + k0 + ac);
            int br = c >> 5, bc = (c & 31) << 2;   // 32 rows x 128 cols
            cp_async16(smem_u32(&sB[st * BSTG + br * 136 + bc]),
                       W + (size_t)(k0 + br) * N + col0 + bc);
        }
        cp_commit();
    };

    int NK = K >> 5;
    prefetch(0, 0);
    prefetch(1, 32);
    for (int kt = 0; kt < NK; kt++) {
        if (kt + 1 < NK) cp_wait<1>(); else cp_wait<0>();
        __syncthreads();
        if (kt + 2 < NK) prefetch((kt + 2) % 3, (kt + 2) << 5);

        int st = kt % 3;
        const uint32_t* pa = sA + st * ASTG;
        const uint32_t* pb = sB + st * BSTG;
        #pragma unroll
        for (int kk = 0; kk < 32; kk += 8) {
            uint32_t af[2][4], bf[8][2];
            #pragma unroll
            for (int mi = 0; mi < 2; mi++) {
                int mb = wm * 32 + mi * 16;
                af[mi][0] = pa[(mb + g) * 36 + kk + tq];
                af[mi][1] = pa[(mb + g + 8) * 36 + kk + tq];
                af[mi][2] = pa[(mb + g) * 36 + kk + tq + 4];
                af[mi][3] = pa[(mb + g + 8) * 36 + kk + tq + 4];
            }
            #pragma unroll
            for (int ni = 0; ni < 8; ni++) {
                int nb = wn * 64 + ni * 8;
                bf[ni][0] = pb[(kk + tq) * 136 + nb + g];
                bf[ni][1] = pb[(kk + tq + 4) * 136 + nb + g];
            }
            #pragma unroll
            for (int mi = 0; mi < 2; mi++)
                #pragma unroll
                for (int ni = 0; ni < 8; ni++)
                    mma_tf32(acc[mi][ni], af[mi], bf[ni]);
        }
    }

    #pragma unroll
    for (int mi = 0; mi < 2; mi++) {
        int rA = row0 + wm * 32 + mi * 16 + g;
        int rB = rA + 8;
        #pragma unroll
        for (int ni = 0; ni < 8; ni++) {
            int cg = col0 + wn * 64 + ni * 8 + 2 * tq;
            float b0 = bias[cg], b1 = bias[cg + 1];
            float v0 = acc[mi][ni][0] + b0;
            float v1 = acc[mi][ni][1] + b1;
            float v2 = acc[mi][ni][2] + b0;
            float v3 = acc[mi][ni][3] + b1;
            if (EPI == 1) {
                v0 = gelu_f(v0); v1 = gelu_f(v1);
                v2 = gelu_f(v2); v3 = gelu_f(v3);
            }
            if (EPI == 2) {
                v0 += R[(size_t)rA * N + cg];
                v1 += R[(size_t)rA * N + cg + 1];
                v2 += R[(size_t)rB * N + cg];
                v3 += R[(size_t)rB * N + cg + 1];
            }
            if (OTF) {
                uint32_t* Cu = (uint32_t*)C;
                *(uint2*)&Cu[(size_t)rA * N + cg] = make_uint2(f2tf(v0), f2tf(v1));
                *(uint2*)&Cu[(size_t)rB * N + cg] = make_uint2(f2tf(v2), f2tf(v3));
            } else {
                *(float2*)&C[(size_t)rA * N + cg] = make_float2(v0, v1);
                *(float2*)&C[(size_t)rB * N + cg] = make_float2(v2, v3);
            }
        }
    }
}

// ---------------- KV assembly ----------------
__global__ void copy_past_k(const float* __restrict__ kin) {
    int idx = blockIdx.x * blockDim.x + threadIdx.x;
    int e = idx * 4;
    int bhd = e >> 10;
    int t   = e & 1023;
    *(float4*)&g_Kall[(size_t)bhd * T_ + t] = *(const float4*)&kin[e];
}

__global__ void copy_past_v(const float* __restrict__ vin) {
    int idx = blockIdx.x * blockDim.x + threadIdx.x;
    int e = idx * 4;
    int bh  = e >> 16;
    int rem = e & 65535;
    *(float4*)&g_Vall[(size_t)bh * T_ * DH_ + rem] = *(const float4*)&vin[e];
}

__global__ void scatter_kv(const float* __restrict__ qkv,
                           float* __restrict__ outk, float* __restrict__ outv) {
    int idx = blockIdx.x * blockDim.x + threadIdx.x;
    int bs = idx >> 10;
    int hd = idx & 1023;
    int b = bs >> 10, s = bs & 1023;
    int h = hd >> 6,  d = hd & 63;
    float kkv = qkv[(size_t)bs * D3_ + D_     + hd];
    float vvv = qkv[(size_t)bs * D3_ + 2 * D_ + hd];
    size_t kpos = (size_t)(b * H_ + h) * DH_ + d;
    g_Kall[kpos * T_ + P_ + s] = kkv;
    outk[kpos * S_ + s] = kkv;
    size_t vrow = (size_t)(b * H_ + h) * T_ + P_ + s;
    g_Vall[vrow * DH_ + d] = vvv;
    outv[((size_t)(b * H_ + h) * S_ + s) * DH_ + d] = vvv;
}

// ---------------- flash attention, tf32 MMA (Br=64, Bc=64, 4 warps) ----------------
__global__ __launch_bounds__(128)
void attn_mma_kernel(const float* __restrict__ qkv, uint32_t* __restrict__ Ab) {
    extern __shared__ uint32_t smu[];
    uint32_t (*Qs)[72] = (uint32_t(*)[72])smu;
    uint32_t (*Ks)[72] = (uint32_t(*)[72])(smu + 64 * 72);
    uint32_t (*Vs)[72] = (uint32_t(*)[72])(smu + 2 * 64 * 72);

    int bh = blockIdx.x, b = bh >> 4, h = bh & 15;
    int s0 = blockIdx.y * 64;
    int tid = threadIdx.x, lane = tid & 31, wid = tid >> 5;
    int g = lane >> 2, tq = lane & 3;
    int mb = wid * 16;

    for (int it = tid; it < 1024; it += 128) {
        int r = it >> 4, c = (it & 15) << 2;
        float4 v = *(const float4*)&qkv[(size_t)(b * S_ + s0 + r) * D3_ + h * DH_ + c];
        Qs[r][c + 0] = f2tf(v.x); Qs[r][c + 1] = f2tf(v.y);
        Qs[r][c + 2] = f2tf(v.z); Qs[r][c + 3] = f2tf(v.w);
    }
    const float* Kb = g_Kall + (size_t)bh * DH_ * T_;
    const float* Vb = g_Vall + (size_t)bh * T_ * DH_;

    float m0 = -INFINITY, m1 = -INFINITY, l0 = 0.f, l1 = 0.f;
    float O[8][4];
    #pragma unroll
    for (int nd = 0; nd < 8; nd++)
        #pragma unroll
        for (int r = 0; r < 4; r++) O[nd][r] = 0.f;

    for (int t0 = 0; t0 < T_; t0 += 64) {
        __syncthreads();
        for (int it = tid; it < 1024; it += 128) {
            int r = it >> 4, c = (it & 15) << 2;
            float4 kv = *(const float4*)&Kb[(size_t)r * T_ + t0 + c];
            Ks[r][c + 0] = f2tf(kv.x); Ks[r][c + 1] = f2tf(kv.y);
            Ks[r][c + 2] = f2tf(kv.z); Ks[r][c + 3] = f2tf(kv.w);
            float4 vv = *(const float4*)&Vb[(size_t)(t0 + r) * DH_ + c];
            Vs[r][c + 0] = f2tf(vv.x); Vs[r][c + 1] = f2tf(vv.y);
            Vs[r][c + 2] = f2tf(vv.z); Vs[r][c + 3] = f2tf(vv.w);
        }
        __syncthreads();

        float sv[8][4];
        #pragma unroll
        for (int ni = 0; ni < 8; ni++)
            #pragma unroll
            for (int r = 0; r < 4; r++) sv[ni][r] = 0.f;

        #pragma unroll
        for (int kk = 0; kk < 64; kk += 8) {
            uint32_t af[4];
            af[0] = Qs[mb + g][kk + tq];
            af[1] = Qs[mb + g + 8][kk + tq];
            af[2] = Qs[mb + g][kk + tq + 4];
            af[3] = Qs[mb + g + 8][kk + tq + 4];
            #pragma unroll
            for (int ni = 0; ni < 8; ni++) {
                uint32_t bf[2] = { Ks[kk + tq][ni * 8 + g], Ks[kk + tq + 4][ni * 8 + g] };
                mma_tf32(sv[ni], af, bf);
            }
        }

        float mx0 = -INFINITY, mx1 = -INFINITY;
        #pragma unroll
        for (int ni = 0; ni < 8; ni++) {
            mx0 = fmaxf(mx0, fmaxf(sv[ni][0], sv[ni][1]));
            mx1 = fmaxf(mx1, fmaxf(sv[ni][2], sv[ni][3]));
        }
        mx0 = fmaxf(mx0, __shfl_xor_sync(0xffffffffu, mx0, 1));
        mx0 = fmaxf(mx0, __shfl_xor_sync(0xffffffffu, mx0, 2));
        mx1 = fmaxf(mx1, __shfl_xor_sync(0xffffffffu, mx1, 1));
        mx1 = fmaxf(mx1, __shfl_xor_sync(0xffffffffu, mx1, 2));
        float mn0 = fmaxf(m0, mx0), mn1 = fmaxf(m1, mx1);
        float sc0 = __expf(m0 - mn0), sc1 = __expf(m1 - mn1);
        float ps0 = 0.f, ps1 = 0.f;
        #pragma unroll
        for (int ni = 0; ni < 8; ni++) {
            sv[ni][0] = __expf(sv[ni][0] - mn0);
            sv[ni][1] = __expf(sv[ni][1] - mn0);
            sv[ni][2] = __expf(sv[ni][2] - mn1);
            sv[ni][3] = __expf(sv[ni][3] - mn1);
            ps0 += sv[ni][0] + sv[ni][1];
            ps1 += sv[ni][2] + sv[ni][3];
        }
        ps0 += __shfl_xor_sync(0xffffffffu, ps0, 1);
        ps0 += __shfl_xor_sync(0xffffffffu, ps0, 2);
        ps1 += __shfl_xor_sync(0xffffffffu, ps1, 1);
        ps1 += __shfl_xor_sync(0xffffffffu, ps1, 2);
        l0 = l0 * sc0 + ps0;
        l1 = l1 * sc1 + ps1;
        m0 = mn0; m1 = mn1;
        #pragma unroll
        for (int nd = 0; nd < 8; nd++) {
            O[nd][0] *= sc0; O[nd][1] *= sc0;
            O[nd][2] *= sc1; O[nd][3] *= sc1;
        }

        #pragma unroll
        for (int ni = 0; ni < 8; ni++) {
            int sl0 = (g << 2) + (tq >> 1);
            int sl1 = sl0 + 2;
            float v00 = __shfl_sync(0xffffffffu, sv[ni][0], sl0);
            float v01 = __shfl_sync(0xffffffffu, sv[ni][1], sl0);
            float v10 = __shfl_sync(0xffffffffu, sv[ni][0], sl1);
            float v11 = __shfl_sync(0xffffffffu, sv[ni][1], sl1);
            float w00 = __shfl_sync(0xffffffffu, sv[ni][2], sl0);
            float w01 = __shfl_sync(0xffffffffu, sv[ni][3], sl0);
            float w10 = __shfl_sync(0xffffffffu, sv[ni][2], sl1);
            float w11 = __shfl_sync(0xffffffffu, sv[ni][3], sl1);
            bool odd = (tq & 1);
            uint32_t af[4];
            af[0] = f2tf(odd ? v01 : v00);
            af[1] = f2tf(odd ? w01 : w00);
            af[2] = f2tf(odd ? v11 : v10);
            af[3] = f2tf(odd ? w11 : w10);
            #pragma unroll
            for (int nd = 0; nd < 8; nd++) {
                uint32_t bf[2] = { Vs[ni * 8 + tq][nd * 8 + g], Vs[ni * 8 + tq + 4][nd * 8 + g] };
                mma_tf32(O[nd], af, bf);
            }
        }
    }

    float inv0 = 1.0f / l0, inv1 = 1.0f / l1;
    int rA = s0 + mb + g, rB = rA + 8;
    #pragma unroll
    for (int nd = 0; nd < 8; nd++) {
        int col = h * DH_ + nd * 8 + 2 * tq;
        *(uint2*)&Ab[(size_t)(b * S_ + rA) * D_ + col] =
            make_uint2(f2tf(O[nd][0] * inv0), f2tf(O[nd][1] * inv0));
        *(uint2*)&Ab[(size_t)(b * S_ + rB) * D_ + col] =
            make_uint2(f2tf(O[nd][2] * inv1), f2tf(O[nd][3] * inv1));
    }
}

// ---------------- launch ----------------
extern "C" void kernel_launch(void* const* d_in, const int* in_sizes, int n_in,
                              void* d_out, int out_size) {
    const float* x      = (const float*)d_in[0];
    const float* kin    = (const float*)d_in[1];
    const float* vin    = (const float*)d_in[2];
    const float* ln1w   = (const float*)d_in[3];
    const float* ln1b   = (const float*)d_in[4];
    const float* ln2w   = (const float*)d_in[5];
    const float* ln2b   = (const float*)d_in[6];
    const float* w_attn = (const float*)d_in[7];
    const float* b_attn = (const float*)d_in[8];
    const float* w_proj = (const float*)d_in[9];
    const float* b_proj = (const float*)d_in[10];
    const float* w_fc   = (const float*)d_in[11];
    const float* b_fc   = (const float*)d_in[12];
    const float* w_fc2  = (const float*)d_in[13];
    const float* b_fc2  = (const float*)d_in[14];

    float* out_x = (float*)d_out;
    float* out_k = out_x + (size_t)NT_ * D_;
    float* out_v = out_k + (size_t)NT_ * D_;

    uint32_t *ph, *pa, *ph2, *pm, *pwa, *pwp, *pwf, *pwf2;
    float *pqkv, *px1;
    cudaGetSymbolAddress((void**)&ph,   g_h);
    cudaGetSymbolAddress((void**)&pqkv, g_qkv);
    cudaGetSymbolAddress((void**)&pa,   g_a);
    cudaGetSymbolAddress((void**)&px1,  g_x1);
    cudaGetSymbolAddress((void**)&ph2,  g_h2);
    cudaGetSymbolAddress((void**)&pm,   g_m);
    cudaGetSymbolAddress((void**)&pwa,  g_wattn_t);
    cudaGetSymbolAddress((void**)&pwp,  g_wproj_t);
    cudaGetSymbolAddress((void**)&pwf,  g_wfc_t);
    cudaGetSymbolAddress((void**)&pwf2, g_wfc2_t);

    cudaFuncSetAttribute(tgemm_kernel<0,0>, cudaFuncAttributeMaxDynamicSharedMemorySize, TG_SMEM);
    cudaFuncSetAttribute(tgemm_kernel<2,0>, cudaFuncAttributeMaxDynamicSharedMemorySize, TG_SMEM);
    cudaFuncSetAttribute(tgemm_kernel<1,1>, cudaFuncAttributeMaxDynamicSharedMemorySize, TG_SMEM);
    int attn_smem = 3 * 64 * 72 * (int)sizeof(uint32_t);  // 55296
    cudaFuncSetAttribute(attn_mma_kernel, cudaFuncAttributeMaxDynamicSharedMemorySize, attn_smem);

    // 1: w_attn conversion
    conv_tf32_kernel<<<(D_*D3_/4 + 255)/256, 256>>>((const float4*)w_attn, (uint4*)pwa, D_*D3_/4);
    // 2: ln1
    ln_kernel<<<NT_, 256>>>(x, ln1w, ln1b, ph);
    // 3: past-K copy
    copy_past_k<<<2048, 256>>>(kin);
    // 4: qkv gemm  <-- profiled slot
    tgemm_kernel<0,0><<<dim3(D3_ / 128, NT_ / 128), 256, TG_SMEM>>>(ph, pwa, b_attn, nullptr,
                                                                    pqkv, NT_, D3_, D_);
    // 5: past-V copy
    copy_past_v<<<2048, 256>>>(vin);
    // 6: scatter new KV
    scatter_kv<<<8192, 256>>>(pqkv, out_k, out_v);
    // 7: attention
    attn_mma_kernel<<<dim3(B_ * H_, S_ / 64), 128, attn_smem>>>(pqkv, pa);
    // 8: w_proj conversion
    conv_tf32_kernel<<<(D_*D_/4 + 255)/256, 256>>>((const float4*)w_proj, (uint4*)pwp, D_*D_/4);
    // 9: proj + residual
    tgemm_kernel<2,0><<<dim3(D_ / 128, NT_ / 128), 256, TG_SMEM>>>(pa, pwp, b_proj, x,
                                                                   px1, NT_, D_, D_);
    // 10: ln2
    ln_kernel<<<NT_, 256>>>(px1, ln2w, ln2b, ph2);
    // 11: w_fc conversion
    conv_tf32_kernel<<<(D_*D4_/4 + 255)/256, 256>>>((const float4*)w_fc, (uint4*)pwf, D_*D4_/4);
    // 12: fc + gelu -> tf32
    tgemm_kernel<1,1><<<dim3(D4_ / 128, NT_ / 128), 256, TG_SMEM>>>(ph2, pwf, b_fc, nullptr,
                                                                    (float*)pm, NT_, D4_, D_);
    // 13: w_fc2 conversion
    conv_tf32_kernel<<<(D4_*D_/4 + 255)/256, 256>>>((const float4*)w_fc2, (uint4*)pwf2, D4_*D_/4);
    // 14: fc2 + residual -> out x
    tgemm_kernel<2,0><<<dim3(D_ / 128, NT_ / 128), 256, TG_SMEM>>>(pm, pwf2, b_fc2, px1,
                                                                   out_x, NT_, D_, D4_);
}

// round 11
// speedup vs baseline: 1.3799x; 1.0093x over previous
#include <cuda_runtime.h>
#include <math.h>
#include <stdint.h>

#define B_  2
#define S_  1024
#define P_  1024
#define D_  1024
#define H_  16
#define DH_ 64
#define T_  2048   // P + S
#define NT_ 2048   // B * S tokens
#define D3_ 3072
#define D4_ 4096

// ---------------- scratch ----------------
__device__ uint32_t g_h   [NT_ * D_];        // ln1 out (tf32 bits)
__device__ float    g_qkv [NT_ * D3_];
__device__ uint32_t g_Kall[B_*H_*DH_*T_];    // [b,h,d,t]  tf32 bits
__device__ uint32_t g_Vall[B_*H_*T_*DH_];    // [b,h,t,d]  tf32 bits
__device__ uint32_t g_a   [NT_ * D_];        // attn out (tf32 bits)
__device__ float    g_x1  [NT_ * D_];
__device__ uint32_t g_h2  [NT_ * D_];        // ln2 out (tf32 bits)
__device__ uint32_t g_m   [NT_ * D4_];       // mlp hidden (tf32 bits)
__device__ uint32_t g_wattn_t[D_ * D3_];
__device__ uint32_t g_wproj_t[D_ * D_];
__device__ uint32_t g_wfc_t  [D_ * D4_];
__device__ uint32_t g_wfc2_t [D4_ * D_];

// ---------------- helpers ----------------
__device__ __forceinline__ uint32_t smem_u32(const void* p) {
    return (uint32_t)__cvta_generic_to_shared(p);
}
__device__ __forceinline__ void cp_async16(uint32_t saddr, const void* g) {
    asm volatile("cp.async.cg.shared.global [%0], [%1], 16;\n" :: "r"(saddr), "l"(g));
}
__device__ __forceinline__ void cp_commit() {
    asm volatile("cp.async.commit_group;\n");
}
template<int N>
__device__ __forceinline__ void cp_wait() {
    asm volatile("cp.async.wait_group %0;\n" :: "n"(N));
}
__device__ __forceinline__ uint32_t f2tf(float v) {
    uint32_t r;
    asm("cvt.rna.tf32.f32 %0, %1;" : "=r"(r) : "f"(v));
    return r;
}
__device__ __forceinline__ void mma_tf32(float* d, const uint32_t* a, const uint32_t* b) {
    asm volatile(
        "mma.sync.aligned.m16n8k8.row.col.f32.tf32.tf32.f32 "
        "{%0,%1,%2,%3}, {%4,%5,%6,%7}, {%8,%9}, {%0,%1,%2,%3};"
        : "+f"(d[0]), "+f"(d[1]), "+f"(d[2]), "+f"(d[3])
        : "r"(a[0]), "r"(a[1]), "r"(a[2]), "r"(a[3]), "r"(b[0]), "r"(b[1]));
}
__device__ __forceinline__ float gelu_f(float x) {
    float x3 = x * x * x;
    return 0.5f * x * (1.0f + tanhf(0.7978845608028654f * (x + 0.044715f * x3)));
}

// ---------------- weight pre-conversion ----------------
__global__ void conv_tf32_kernel(const float4* __restrict__ src, uint4* __restrict__ dst,
                                 int n4) {
    int i = blockIdx.x * blockDim.x + threadIdx.x;
    if (i < n4) {
        float4 v = src[i];
        uint4 o;
        o.x = f2tf(v.x); o.y = f2tf(v.y); o.z = f2tf(v.z); o.w = f2tf(v.w);
        dst[i] = o;
    }
}

// ---------------- layernorm -> tf32 bits ----------------
__global__ void ln_kernel(const float* __restrict__ X, const float* __restrict__ w,
                          const float* __restrict__ bia, uint32_t* __restrict__ Y) {
    __shared__ float red1[8];
    __shared__ float red2[8];
    int row = blockIdx.x;
    int tid = threadIdx.x;
    float4 v = ((const float4*)(X + (size_t)row * D_))[tid];
    float s = v.x + v.y + v.z + v.w;
    #pragma unroll
    for (int o = 16; o; o >>= 1) s += __shfl_xor_sync(0xffffffffu, s, o);
    if ((tid & 31) == 0) red1[tid >> 5] = s;
    __syncthreads();
    float u = 0.f;
    #pragma unroll
    for (int i = 0; i < 8; i++) u += red1[i];
    u *= (1.0f / D_);
    float dx = v.x - u, dy = v.y - u, dz = v.z - u, dw = v.w - u;
    float q = dx*dx + dy*dy + dz*dz + dw*dw;
    #pragma unroll
    for (int o = 16; o; o >>= 1) q += __shfl_xor_sync(0xffffffffu, q, o);
    if ((tid & 31) == 0) red2[tid >> 5] = q;
    __syncthreads();
    float var = 0.f;
    #pragma unroll
    for (int i = 0; i < 8; i++) var += red2[i];
    var *= (1.0f / D_);
    float inv = rsqrtf(var + 1e-12f);
    float4 wv = ((const float4*)w)[tid];
    float4 bv = ((const float4*)bia)[tid];
    uint4 o;
    o.x = f2tf(wv.x * (dx * inv) + bv.x);
    o.y = f2tf(wv.y * (dy * inv) + bv.y);
    o.z = f2tf(wv.z * (dz * inv) + bv.z);
    o.w = f2tf(wv.w * (dw * inv) + bv.w);
    ((uint4*)(Y + (size_t)row * D_))[tid] = o;
}

// ---------------- tf32 GEMM: 128x128x32 tile, 3-stage pipeline (R10) -----------
#define ASTG 4608
#define BSTG 4352
#define TG_SMEM (3 * (ASTG + BSTG) * 4)   // 107520

template<int EPI, int OTF>
__global__ __launch_bounds__(256)
void tgemm_kernel(const uint32_t* __restrict__ A, const uint32_t* __restrict__ W,
                  const float* __restrict__ bias, const float* __restrict__ R,
                  float* __restrict__ C, int M, int N, int K) {
    extern __shared__ uint32_t smg[];
    uint32_t* sA = smg;
    uint32_t* sB = smg + 3 * ASTG;

    int tid = threadIdx.x, lane = tid & 31, wid = tid >> 5;
    int wm = wid >> 1, wn = wid & 1;
    int row0 = blockIdx.y * 128, col0 = blockIdx.x * 128;
    int g = lane >> 2, tq = lane & 3;

    float acc[2][8][4];
    #pragma unroll
    for (int mi = 0; mi < 2; mi++)
        #pragma unroll
        for (int ni = 0; ni < 8; ni++)
            #pragma unroll
            for (int r = 0; r < 4; r++) acc[mi][ni][r] = 0.f;

    auto prefetch = [&](int st, int k0) {
        #pragma unroll
        for (int i = 0; i < 4; i++) {
            int c = tid + 256 * i;
            int ar = c >> 3, ac = (c & 7) << 2;
            cp_async16(smem_u32(&sA[st * ASTG + ar * 36 + ac]),
                       A + (size_t)(row0 + ar) * K + k0 + ac);
            int br = c >> 5, bc = (c & 31) << 2;
            cp_async16(smem_u32(&sB[st * BSTG + br * 136 + bc]),
                       W + (size_t)(k0 + br) * N + col0 + bc);
        }
        cp_commit();
    };

    int NK = K >> 5;
    prefetch(0, 0);
    prefetch(1, 32);
    for (int kt = 0; kt < NK; kt++) {
        if (kt + 1 < NK) cp_wait<1>(); else cp_wait<0>();
        __syncthreads();
        if (kt + 2 < NK) prefetch((kt + 2) % 3, (kt + 2) << 5);

        int st = kt % 3;
        const uint32_t* pa = sA + st * ASTG;
        const uint32_t* pb = sB + st * BSTG;
        #pragma unroll
        for (int kk = 0; kk < 32; kk += 8) {
            uint32_t af[2][4], bf[8][2];
            #pragma unroll
            for (int mi = 0; mi < 2; mi++) {
                int mb = wm * 32 + mi * 16;
                af[mi][0] = pa[(mb + g) * 36 + kk + tq];
                af[mi][1] = pa[(mb + g + 8) * 36 + kk + tq];
                af[mi][2] = pa[(mb + g) * 36 + kk + tq + 4];
                af[mi][3] = pa[(mb + g + 8) * 36 + kk + tq + 4];
            }
            #pragma unroll
            for (int ni = 0; ni < 8; ni++) {
                int nb = wn * 64 + ni * 8;
                bf[ni][0] = pb[(kk + tq) * 136 + nb + g];
                bf[ni][1] = pb[(kk + tq + 4) * 136 + nb + g];
            }
            #pragma unroll
            for (int mi = 0; mi < 2; mi++)
                #pragma unroll
                for (int ni = 0; ni < 8; ni++)
                    mma_tf32(acc[mi][ni], af[mi], bf[ni]);
        }
    }

    #pragma unroll
    for (int mi = 0; mi < 2; mi++) {
        int rA = row0 + wm * 32 + mi * 16 + g;
        int rB = rA + 8;
        #pragma unroll
        for (int ni = 0; ni < 8; ni++) {
            int cg = col0 + wn * 64 + ni * 8 + 2 * tq;
            float b0 = bias[cg], b1 = bias[cg + 1];
            float v0 = acc[mi][ni][0] + b0;
            float v1 = acc[mi][ni][1] + b1;
            float v2 = acc[mi][ni][2] + b0;
            float v3 = acc[mi][ni][3] + b1;
            if (EPI == 1) {
                v0 = gelu_f(v0); v1 = gelu_f(v1);
                v2 = gelu_f(v2); v3 = gelu_f(v3);
            }
            if (EPI == 2) {
                v0 += R[(size_t)rA * N + cg];
                v1 += R[(size_t)rA * N + cg + 1];
                v2 += R[(size_t)rB * N + cg];
                v3 += R[(size_t)rB * N + cg + 1];
            }
            if (OTF) {
                uint32_t* Cu = (uint32_t*)C;
                *(uint2*)&Cu[(size_t)rA * N + cg] = make_uint2(f2tf(v0), f2tf(v1));
                *(uint2*)&Cu[(size_t)rB * N + cg] = make_uint2(f2tf(v2), f2tf(v3));
            } else {
                *(float2*)&C[(size_t)rA * N + cg] = make_float2(v0, v1);
                *(float2*)&C[(size_t)rB * N + cg] = make_float2(v2, v3);
            }
        }
    }
}

// ---------------- KV assembly (caches hold tf32 bits) ----------------
__global__ void copy_past_k(const float* __restrict__ kin) {
    int idx = blockIdx.x * blockDim.x + threadIdx.x;
    int e = idx * 4;
    int bhd = e >> 10;
    int t   = e & 1023;
    float4 v = *(const float4*)&kin[e];
    uint4 o;
    o.x = f2tf(v.x); o.y = f2tf(v.y); o.z = f2tf(v.z); o.w = f2tf(v.w);
    *(uint4*)&g_Kall[(size_t)bhd * T_ + t] = o;
}

__global__ void copy_past_v(const float* __restrict__ vin) {
    int idx = blockIdx.x * blockDim.x + threadIdx.x;
    int e = idx * 4;
    int bh  = e >> 16;
    int rem = e & 65535;
    float4 v = *(const float4*)&vin[e];
    uint4 o;
    o.x = f2tf(v.x); o.y = f2tf(v.y); o.z = f2tf(v.z); o.w = f2tf(v.w);
    *(uint4*)&g_Vall[(size_t)bh * T_ * DH_ + rem] = o;
}

__global__ void scatter_kv(const float* __restrict__ qkv,
                           float* __restrict__ outk, float* __restrict__ outv) {
    int idx = blockIdx.x * blockDim.x + threadIdx.x;
    int bs = idx >> 10;
    int hd = idx & 1023;
    int b = bs >> 10, s = bs & 1023;
    int h = hd >> 6,  d = hd & 63;
    float kkv = qkv[(size_t)bs * D3_ + D_     + hd];
    float vvv = qkv[(size_t)bs * D3_ + 2 * D_ + hd];
    size_t kpos = (size_t)(b * H_ + h) * DH_ + d;
    g_Kall[kpos * T_ + P_ + s] = f2tf(kkv);
    outk[kpos * S_ + s] = kkv;
    size_t vrow = (size_t)(b * H_ + h) * T_ + P_ + s;
    g_Vall[vrow * DH_ + d] = f2tf(vvv);
    outv[((size_t)(b * H_ + h) * S_ + s) * DH_ + d] = vvv;
}

// ---------------- flash attention, tf32 MMA (Br=128, Bc=64, 8 warps) -----------
#define ATTN_SMEM ((128 + 64 + 64) * 72 * 4)   // 73728

__global__ __launch_bounds__(256)
void attn_mma_kernel(const float* __restrict__ qkv, uint32_t* __restrict__ Ab) {
    extern __shared__ uint32_t smu[];
    uint32_t (*Qs)[72] = (uint32_t(*)[72])smu;                   // 128 rows
    uint32_t (*Ks)[72] = (uint32_t(*)[72])(smu + 128 * 72);      // K^T[d][j]
    uint32_t (*Vs)[72] = (uint32_t(*)[72])(smu + 192 * 72);      // V[j][d]

    int bh = blockIdx.x, b = bh >> 4, h = bh & 15;
    int s0 = blockIdx.y * 128;
    int tid = threadIdx.x, lane = tid & 31, wid = tid >> 5;
    int g = lane >> 2, tq = lane & 3;
    int mb = wid * 16;

    // Q fill: 128 rows x 64 cols (cvt once)
    for (int it = tid; it < 2048; it += 256) {
        int r = it >> 4, c = (it & 15) << 2;
        float4 v = *(const float4*)&qkv[(size_t)(b * S_ + s0 + r) * D3_ + h * DH_ + c];
        Qs[r][c + 0] = f2tf(v.x); Qs[r][c + 1] = f2tf(v.y);
        Qs[r][c + 2] = f2tf(v.z); Qs[r][c + 3] = f2tf(v.w);
    }
    const uint32_t* Kb = g_Kall + (size_t)bh * DH_ * T_;
    const uint32_t* Vb = g_Vall + (size_t)bh * T_ * DH_;

    float m0 = -INFINITY, m1 = -INFINITY, l0 = 0.f, l1 = 0.f;
    float O[8][4];
    #pragma unroll
    for (int nd = 0; nd < 8; nd++)
        #pragma unroll
        for (int r = 0; r < 4; r++) O[nd][r] = 0.f;

    for (int t0 = 0; t0 < T_; t0 += 64) {
        __syncthreads();
        // K/V fill: plain tf32-bit copies, no cvt
        for (int it = tid; it < 1024; it += 256) {
            int r = it >> 4, c = (it & 15) << 2;
            *(uint4*)&Ks[r][c] = *(const uint4*)&Kb[(size_t)r * T_ + t0 + c];
            *(uint4*)&Vs[r][c] = *(const uint4*)&Vb[(size_t)(t0 + r) * DH_ + c];
        }
        __syncthreads();

        float sv[8][4];
        #pragma unroll
        for (int ni = 0; ni < 8; ni++)
            #pragma unroll
            for (int r = 0; r < 4; r++) sv[ni][r] = 0.f;

        #pragma unroll
        for (int kk = 0; kk < 64; kk += 8) {
            uint32_t af[4];
            af[0] = Qs[mb + g][kk + tq];
            af[1] = Qs[mb + g + 8][kk + tq];
            af[2] = Qs[mb + g][kk + tq + 4];
            af[3] = Qs[mb + g + 8][kk + tq + 4];
            #pragma unroll
            for (int ni = 0; ni < 8; ni++) {
                uint32_t bf[2] = { Ks[kk + tq][ni * 8 + g], Ks[kk + tq + 4][ni * 8 + g] };
                mma_tf32(sv[ni], af, bf);
            }
        }

        float mx0 = -INFINITY, mx1 = -INFINITY;
        #pragma unroll
        for (int ni = 0; ni < 8; ni++) {
            mx0 = fmaxf(mx0, fmaxf(sv[ni][0], sv[ni][1]));
            mx1 = fmaxf(mx1, fmaxf(sv[ni][2], sv[ni][3]));
        }
        mx0 = fmaxf(mx0, __shfl_xor_sync(0xffffffffu, mx0, 1));
        mx0 = fmaxf(mx0, __shfl_xor_sync(0xffffffffu, mx0, 2));
        mx1 = fmaxf(mx1, __shfl_xor_sync(0xffffffffu, mx1, 1));
        mx1 = fmaxf(mx1, __shfl_xor_sync(0xffffffffu, mx1, 2));
        float mn0 = fmaxf(m0, mx0), mn1 = fmaxf(m1, mx1);
        float sc0 = __expf(m0 - mn0), sc1 = __expf(m1 - mn1);
        float ps0 = 0.f, ps1 = 0.f;
        #pragma unroll
        for (int ni = 0; ni < 8; ni++) {
            sv[ni][0] = __expf(sv[ni][0] - mn0);
            sv[ni][1] = __expf(sv[ni][1] - mn0);
            sv[ni][2] = __expf(sv[ni][2] - mn1);
            sv[ni][3] = __expf(sv[ni][3] - mn1);
            ps0 += sv[ni][0] + sv[ni][1];
            ps1 += sv[ni][2] + sv[ni][3];
        }
        ps0 += __shfl_xor_sync(0xffffffffu, ps0, 1);
        ps0 += __shfl_xor_sync(0xffffffffu, ps0, 2);
        ps1 += __shfl_xor_sync(0xffffffffu, ps1, 1);
        ps1 += __shfl_xor_sync(0xffffffffu, ps1, 2);
        l0 = l0 * sc0 + ps0;
        l1 = l1 * sc1 + ps1;
        m0 = mn0; m1 = mn1;
        #pragma unroll
        for (int nd = 0; nd < 8; nd++) {
            O[nd][0] *= sc0; O[nd][1] *= sc0;
            O[nd][2] *= sc1; O[nd][3] *= sc1;
        }

        #pragma unroll
        for (int ni = 0; ni < 8; ni++) {
            int sl0 = (g << 2) + (tq >> 1);
            int sl1 = sl0 + 2;
            float v00 = __shfl_sync(0xffffffffu, sv[ni][0], sl0);
            float v01 = __shfl_sync(0xffffffffu, sv[ni][1], sl0);
            float v10 = __shfl_sync(0xffffffffu, sv[ni][0], sl1);
            float v11 = __shfl_sync(0xffffffffu, sv[ni][1], sl1);
            float w00 = __shfl_sync(0xffffffffu, sv[ni][2], sl0);
            float w01 = __shfl_sync(0xffffffffu, sv[ni][3], sl0);
            float w10 = __shfl_sync(0xffffffffu, sv[ni][2], sl1);
            float w11 = __shfl_sync(0xffffffffu, sv[ni][3], sl1);
            bool odd = (tq & 1);
            uint32_t af[4];
            af[0] = f2tf(odd ? v01 : v00);
            af[1] = f2tf(odd ? w01 : w00);
            af[2] = f2tf(odd ? v11 : v10);
            af[3] = f2tf(odd ? w11 : w10);
            #pragma unroll
            for (int nd = 0; nd < 8; nd++) {
                uint32_t bf[2] = { Vs[ni * 8 + tq][nd * 8 + g], Vs[ni * 8 + tq + 4][nd * 8 + g] };
                mma_tf32(O[nd], af, bf);
            }
        }
    }

    float inv0 = 1.0f / l0, inv1 = 1.0f / l1;
    int rA = s0 + mb + g, rB = rA + 8;
    #pragma unroll
    for (int nd = 0; nd < 8; nd++) {
        int col = h * DH_ + nd * 8 + 2 * tq;
        *(uint2*)&Ab[(size_t)(b * S_ + rA) * D_ + col] =
            make_uint2(f2tf(O[nd][0] * inv0), f2tf(O[nd][1] * inv0));
        *(uint2*)&Ab[(size_t)(b * S_ + rB) * D_ + col] =
            make_uint2(f2tf(O[nd][2] * inv1), f2tf(O[nd][3] * inv1));
    }
}

// ---------------- launch ----------------
extern "C" void kernel_launch(void* const* d_in, const int* in_sizes, int n_in,
                              void* d_out, int out_size) {
    const float* x      = (const float*)d_in[0];
    const float* kin    = (const float*)d_in[1];
    const float* vin    = (const float*)d_in[2];
    const float* ln1w   = (const float*)d_in[3];
    const float* ln1b   = (const float*)d_in[4];
    const float* ln2w   = (const float*)d_in[5];
    const float* ln2b   = (const float*)d_in[6];
    const float* w_attn = (const float*)d_in[7];
    const float* b_attn = (const float*)d_in[8];
    const float* w_proj = (const float*)d_in[9];
    const float* b_proj = (const float*)d_in[10];
    const float* w_fc   = (const float*)d_in[11];
    const float* b_fc   = (const float*)d_in[12];
    const float* w_fc2  = (const float*)d_in[13];
    const float* b_fc2  = (const float*)d_in[14];

    float* out_x = (float*)d_out;
    float* out_k = out_x + (size_t)NT_ * D_;
    float* out_v = out_k + (size_t)NT_ * D_;

    uint32_t *ph, *pa, *ph2, *pm, *pwa, *pwp, *pwf, *pwf2;
    float *pqkv, *px1;
    cudaGetSymbolAddress((void**)&ph,   g_h);
    cudaGetSymbolAddress((void**)&pqkv, g_qkv);
    cudaGetSymbolAddress((void**)&pa,   g_a);
    cudaGetSymbolAddress((void**)&px1,  g_x1);
    cudaGetSymbolAddress((void**)&ph2,  g_h2);
    cudaGetSymbolAddress((void**)&pm,   g_m);
    cudaGetSymbolAddress((void**)&pwa,  g_wattn_t);
    cudaGetSymbolAddress((void**)&pwp,  g_wproj_t);
    cudaGetSymbolAddress((void**)&pwf,  g_wfc_t);
    cudaGetSymbolAddress((void**)&pwf2, g_wfc2_t);

    cudaFuncSetAttribute(tgemm_kernel<0,0>, cudaFuncAttributeMaxDynamicSharedMemorySize, TG_SMEM);
    cudaFuncSetAttribute(tgemm_kernel<2,0>, cudaFuncAttributeMaxDynamicSharedMemorySize, TG_SMEM);
    cudaFuncSetAttribute(tgemm_kernel<1,1>, cudaFuncAttributeMaxDynamicSharedMemorySize, TG_SMEM);
    cudaFuncSetAttribute(attn_mma_kernel, cudaFuncAttributeMaxDynamicSharedMemorySize, ATTN_SMEM);

    // 1: w_attn conversion
    conv_tf32_kernel<<<(D_*D3_/4 + 255)/256, 256>>>((const float4*)w_attn, (uint4*)pwa, D_*D3_/4);
    // 2: ln1
    ln_kernel<<<NT_, 256>>>(x, ln1w, ln1b, ph);
    // 3: past-K copy (-> tf32 bits)
    copy_past_k<<<2048, 256>>>(kin);
    // 4: qkv gemm  <-- profiled slot
    tgemm_kernel<0,0><<<dim3(D3_ / 128, NT_ / 128), 256, TG_SMEM>>>(ph, pwa, b_attn, nullptr,
                                                                    pqkv, NT_, D3_, D_);
    // 5: past-V copy (-> tf32 bits)
    copy_past_v<<<2048, 256>>>(vin);
    // 6: scatter new KV (cache tf32 bits; outputs fp32)
    scatter_kv<<<8192, 256>>>(pqkv, out_k, out_v);
    // 7: attention (Br=128)
    attn_mma_kernel<<<dim3(B_ * H_, S_ / 128), 256, ATTN_SMEM>>>(pqkv, pa);
    // 8: w_proj conversion
    conv_tf32_kernel<<<(D_*D_/4 + 255)/256, 256>>>((const float4*)w_proj, (uint4*)pwp, D_*D_/4);
    // 9: proj + residual
    tgemm_kernel<2,0><<<dim3(D_ / 128, NT_ / 128), 256, TG_SMEM>>>(pa, pwp, b_proj, x,
                                                                   px1, NT_, D_, D_);
    // 10: ln2
    ln_kernel<<<NT_, 256>>>(px1, ln2w, ln2b, ph2);
    // 11: w_fc conversion
    conv_tf32_kernel<<<(D_*D4_/4 + 255)/256, 256>>>((const float4*)w_fc, (uint4*)pwf, D_*D4_/4);
    // 12: fc + gelu -> tf32
    tgemm_kernel<1,1><<<dim3(D4_ / 128, NT_ / 128), 256, TG_SMEM>>>(ph2, pwf, b_fc, nullptr,
                                                                    (float*)pm, NT_, D4_, D_);
    // 13: w_fc2 conversion
    conv_tf32_kernel<<<(D4_*D_/4 + 255)/256, 256>>>((const float4*)w_fc2, (uint4*)pwf2, D4_*D_/4);
    // 14: fc2 + residual -> out x
    tgemm_kernel<2,0><<<dim3(D_ / 128, NT_ / 128), 256, TG_SMEM>>>(pm, pwf2, b_fc2, px1,
                                                                   out_x, NT_, D_, D4_);
}